// round 14
// baseline (speedup 1.0000x reference)
#include <cuda_runtime.h>
#include <cuda_fp16.h>
#include <math.h>

#define NN 1000000
#define NE 16000000

// PDL primitives (sm_90+)
#define PDL_TRIGGER() asm volatile("griddepcontrol.launch_dependents;")
#define PDL_WAIT()    asm volatile("griddepcontrol.wait;" ::: "memory")

// ---- scratch (device globals; zero-initialized at load) ----
__device__ float   g_deg[NN];        // re-zeroed by k_final each call
__device__ __half2 g_hs[NN * 8];     // h (then dis*h after k_scale), fp16, 32MB
__device__ __half2 g_agg[NN * 8];    // layer-1 accumulation in fp16, 32MB
__device__ float   g_h2s[NN];        // dis[i]*h2[i]

// ---------------- fused: degree atomics (LTS) + x@W1 (DRAM/FMA) ----------------
#define NB_PROJ 3907            // ceil(NN/256)
#define NB_DEG  15625           // (NE/4)/256 exactly
#define NB_FUSED (NB_PROJ + NB_DEG)

__global__ void __launch_bounds__(256) k_fused(const float* __restrict__ x,
                                               const float* __restrict__ W1,
                                               const int4* __restrict__ dst4,
                                               const float4* __restrict__ ew4) {
    int bid = blockIdx.x;
    if (bid % 5 == 0) {
        __shared__ float sx[256 * 25];
        __shared__ float sW[25 * 16];
        int pb = bid / 5;
        int i0 = pb * 256;
        int nb = min(256, NN - i0);
        int nf4 = (nb * 25) / 4;
        const float4* xg = (const float4*)(x + (size_t)i0 * 25);
        for (int t = threadIdx.x; t < nf4; t += 256) ((float4*)sx)[t] = __ldcs(xg + t);
        for (int t = threadIdx.x; t < 400; t += 256) sW[t] = W1[t];
        __syncthreads();

        int li = threadIdx.x;
        if (li >= nb) return;
        int i = i0 + li;

        float a[16];
#pragma unroll
        for (int f = 0; f < 16; f++) a[f] = 0.0f;
#pragma unroll
        for (int k = 0; k < 25; k++) {
            float xv = sx[li * 25 + k];
#pragma unroll
            for (int f = 0; f < 16; f++) a[f] = fmaf(xv, sW[k * 16 + f], a[f]);
        }

        __half2 hv[8];
#pragma unroll
        for (int q = 0; q < 8; q++)
            hv[q] = __floats2half2_rn(a[2*q], a[2*q + 1]);
        uint4* hp = (uint4*)(g_hs + (size_t)i * 8);
        hp[0] = *(uint4*)&hv[0];
        hp[1] = *(uint4*)&hv[4];
        PDL_TRIGGER();
    } else {
        int db = bid - bid / 5 - 1;
        int tt = db * 256 + threadIdx.x;          // < NE/4 exactly by grid
        int4 d = __ldcs(dst4 + tt);
        float4 w = __ldcs(ew4 + tt);
        atomicAdd(&g_deg[d.x], w.x);
        atomicAdd(&g_deg[d.y], w.y);
        atomicAdd(&g_deg[d.z], w.z);
        atomicAdd(&g_deg[d.w], w.w);
        PDL_TRIGGER();
    }
}

// scale g_hs by dis in place; write agg self-loop seed. 2 nodes/thread.
__global__ void k_scale() {
    PDL_WAIT();
    int base = (blockIdx.x * blockDim.x + threadIdx.x) * 2;
#pragma unroll
    for (int n = 0; n < 2; n++) {
        int i = base + n;
        if (i >= NN) return;
        float s = rsqrtf(g_deg[i] + 1.0f);
        uint4* hp = (uint4*)(g_hs + (size_t)i * 8);
        uint4 p0 = hp[0], p1 = hp[1];
        __half2 hv[8];
        const unsigned* pu = &p0.x;
#pragma unroll
        for (int q = 0; q < 4; q++) {
            float2 f = __half22float2(*(const __half2*)&pu[q]);
            hv[q] = __floats2half2_rn(s * f.x, s * f.y);
        }
        const unsigned* pv = &p1.x;
#pragma unroll
        for (int q = 0; q < 4; q++) {
            float2 f = __half22float2(*(const __half2*)&pv[q]);
            hv[4 + q] = __floats2half2_rn(s * f.x, s * f.y);
        }
        uint4 v0 = *(uint4*)&hv[0];
        uint4 v1 = *(uint4*)&hv[4];
        hp[0] = v0; hp[1] = v1;
        uint4* ap = (uint4*)(g_agg + (size_t)i * 8);
        ap[0] = v0; ap[1] = v1;      // self-loop seed (dis*h)
    }
    PDL_TRIGGER();
}

__device__ __forceinline__ void red_v4h(__half2* addr, unsigned a, unsigned b,
                                        unsigned c, unsigned d) {
    asm volatile("red.global.add.noftz.v4.f16x2 [%0], {%1,%2,%3,%4};"
                 :: "l"(addr), "r"(a), "r"(b), "r"(c), "r"(d)
                 : "memory");
}

// layer-1 edge scatter, paired-lane; streams prefetched pre-wait (pure inputs)
__global__ void __launch_bounds__(256) k_agg1(const int* __restrict__ src,
                                              const int* __restrict__ dst,
                                              const float* __restrict__ ew) {
    int half = threadIdx.x & 1;
    int pair = threadIdx.x >> 1;
    int base = blockIdx.x * 1024;                 // grid covers NE exactly
    int   s[8], d[8];
    float w[8];
#pragma unroll
    for (int j = 0; j < 8; j++) {
        int e = base + j * 128 + pair;
        s[j] = __ldg(src + e);
        d[j] = __ldg(dst + e);
        w[j] = __ldg(ew + e);
    }
    PDL_WAIT();
#pragma unroll
    for (int j = 0; j < 8; j++) {
        uint4 p = __ldg((const uint4*)(g_hs + (size_t)s[j] * 8 + half * 4));
        __half2 wh = __float2half2_rn(w[j]);
        const unsigned* pu = &p.x;
        unsigned m[4];
#pragma unroll
        for (int q = 0; q < 4; q++) {
            __half2 r = __hmul2(wh, *(const __half2*)&pu[q]);
            m[q] = *(unsigned*)&r;
        }
        red_v4h(g_agg + (size_t)d[j] * 8 + half * 4, m[0], m[1], m[2], m[3]);
    }
    PDL_TRIGGER();
}

// layer1 finish: u = dis[i]*agg + b1 -> ELU -> h2 = u@W2
__global__ void k_elu_proj2(const float* __restrict__ b1,
                            const float* __restrict__ W2,
                            float* __restrict__ out) {
    __shared__ float sb1[16], sW2[16];
    if (threadIdx.x < 16) { sb1[threadIdx.x] = b1[threadIdx.x]; sW2[threadIdx.x] = W2[threadIdx.x]; }
    __syncthreads();
    PDL_WAIT();

    int i = blockIdx.x * blockDim.x + threadIdx.x;
    if (i >= NN) return;

    const uint4* ap = (const uint4*)(g_agg + (size_t)i * 8);
    uint4 p0 = __ldcs(ap);
    uint4 p1 = __ldcs(ap + 1);
    float s = rsqrtf(g_deg[i] + 1.0f);
    float acc = 0.0f;
    const unsigned* pu = &p0.x;
#pragma unroll
    for (int q = 0; q < 4; q++) {
        float2 f = __half22float2(*(const __half2*)&pu[q]);
        float u0 = fmaf(s, f.x, sb1[2*q]);
        float u1 = fmaf(s, f.y, sb1[2*q+1]);
        u0 = (u0 > 0.0f) ? u0 : (__expf(u0) - 1.0f);
        u1 = (u1 > 0.0f) ? u1 : (__expf(u1) - 1.0f);
        acc = fmaf(u0, sW2[2*q], acc);
        acc = fmaf(u1, sW2[2*q+1], acc);
    }
    const unsigned* pv = &p1.x;
#pragma unroll
    for (int q = 0; q < 4; q++) {
        float2 f = __half22float2(*(const __half2*)&pv[q]);
        float u0 = fmaf(s, f.x, sb1[8+2*q]);
        float u1 = fmaf(s, f.y, sb1[8+2*q+1]);
        u0 = (u0 > 0.0f) ? u0 : (__expf(u0) - 1.0f);
        u1 = (u1 > 0.0f) ? u1 : (__expf(u1) - 1.0f);
        acc = fmaf(u0, sW2[8+2*q], acc);
        acc = fmaf(u1, sW2[8+2*q+1], acc);
    }
    float hs = s * acc;
    g_h2s[i] = hs;
    out[i] = hs;                                   // self-loop seed
    PDL_TRIGGER();
}

__device__ __forceinline__ void red_f32(float* addr, float v) {
    asm volatile("red.global.add.f32 [%0], %1;" :: "l"(addr), "f"(v) : "memory");
}

// layer-2 edge scatter; 16 edges/thread, streams prefetched pre-wait
__global__ void k_agg2(const int4* __restrict__ src4,
                       const int4* __restrict__ dst4,
                       const float4* __restrict__ ew4,
                       float* __restrict__ out) {
    int t = (blockIdx.x * blockDim.x + threadIdx.x) * 4;
    int4 s[4], d[4];
    float4 w[4];
    bool ok[4];
#pragma unroll
    for (int j = 0; j < 4; j++) {
        int tt = t + j;
        ok[j] = (tt < NE / 4);
        if (ok[j]) {
            s[j] = __ldcs(src4 + tt);
            d[j] = __ldcs(dst4 + tt);
            w[j] = __ldcs(ew4 + tt);
        }
    }
    PDL_WAIT();
#pragma unroll
    for (int j = 0; j < 4; j++) {
        if (!ok[j]) break;
        red_f32(&out[d[j].x], w[j].x * __ldg(&g_h2s[s[j].x]));
        red_f32(&out[d[j].y], w[j].y * __ldg(&g_h2s[s[j].y]));
        red_f32(&out[d[j].z], w[j].z * __ldg(&g_h2s[s[j].z]));
        red_f32(&out[d[j].w], w[j].w * __ldg(&g_h2s[s[j].w]));
    }
    PDL_TRIGGER();
}

// final scale: out = dis*out + b2; re-zero g_deg. 4 nodes/thread, vectorized.
__global__ void k_final(float* __restrict__ out, const float* __restrict__ b2) {
    PDL_WAIT();
    int t = blockIdx.x * blockDim.x + threadIdx.x;
    if (t * 4 >= NN) return;
    float bias = b2[0];
    float4* o4 = (float4*)out;
    float4* g4 = (float4*)g_deg;
    float4 o = o4[t];
    float4 g = g4[t];
    o.x = fmaf(rsqrtf(g.x + 1.0f), o.x, bias);
    o.y = fmaf(rsqrtf(g.y + 1.0f), o.y, bias);
    o.z = fmaf(rsqrtf(g.z + 1.0f), o.z, bias);
    o.w = fmaf(rsqrtf(g.w + 1.0f), o.w, bias);
    o4[t] = o;
    g4[t] = make_float4(0.0f, 0.0f, 0.0f, 0.0f);
}

// ---------------- launch ----------------

static void launch_pdl(const void* func, int grid, int block, void** args) {
    cudaLaunchConfig_t cfg = {};
    cfg.gridDim = dim3(grid, 1, 1);
    cfg.blockDim = dim3(block, 1, 1);
    cfg.dynamicSmemBytes = 0;
    cfg.stream = 0;
    cudaLaunchAttribute attr[1];
    attr[0].id = cudaLaunchAttributeProgrammaticStreamSerialization;
    attr[0].val.programmaticStreamSerializationAllowed = 1;
    cfg.attrs = attr;
    cfg.numAttrs = 1;
    cudaLaunchKernelExC(&cfg, func, args);
}

extern "C" void kernel_launch(void* const* d_in, const int* in_sizes, int n_in,
                              void* d_out, int out_size) {
    const float* x    = (const float*)d_in[0];
    const int*   eidx = (const int*)d_in[1];      // [2, E] int32
    const float* ew   = (const float*)d_in[2];
    const float* W1   = (const float*)d_in[3];
    const float* b1   = (const float*)d_in[4];
    const float* W2   = (const float*)d_in[5];
    const float* b2   = (const float*)d_in[6];
    float* out = (float*)d_out;

    const int*    src  = eidx;
    const int*    dst  = eidx + NE;
    const int4*   src4 = (const int4*)eidx;
    const int4*   dst4 = (const int4*)(eidx + NE);
    const float4* ew4  = (const float4*)ew;

    const int TB = 256;
    int nb_nodes  = (NN + TB - 1) / TB;
    int nb_scale  = (NN / 2 + TB - 1) / TB;
    int nb_final  = (NN / 4 + TB - 1) / TB;        // NN % 4 == 0
    int nb_e16    = (NE / 16 + TB - 1) / TB;
    int nb_agg1   = NE / 1024;

    k_fused<<<NB_FUSED, TB>>>(x, W1, dst4, ew4);
    {
        void* a2[] = {};
        launch_pdl((const void*)k_scale, nb_scale, TB, a2);
    }
    {
        void* a3[] = {(void*)&src, (void*)&dst, (void*)&ew};
        launch_pdl((const void*)k_agg1, nb_agg1, TB, a3);
    }
    {
        void* a4[] = {(void*)&b1, (void*)&W2, (void*)&out};
        launch_pdl((const void*)k_elu_proj2, nb_nodes, TB, a4);
    }
    {
        void* a5[] = {(void*)&src4, (void*)&dst4, (void*)&ew4, (void*)&out};
        launch_pdl((const void*)k_agg2, nb_e16, TB, a5);
    }
    {
        void* a6[] = {(void*)&out, (void*)&b2};
        launch_pdl((const void*)k_final, nb_final, TB, a6);
    }
}

// round 15
// speedup vs baseline: 1.0394x; 1.0394x over previous
#include <cuda_runtime.h>
#include <cuda_fp16.h>
#include <math.h>

#define NN 1000000
#define NE 16000000

// PDL primitives (sm_90+)
#define PDL_TRIGGER() asm volatile("griddepcontrol.launch_dependents;")
#define PDL_WAIT()    asm volatile("griddepcontrol.wait;" ::: "memory")

// ---- scratch (device globals; zero-initialized at load) ----
__device__ float   g_deg[NN];        // re-zeroed by k_final each call
__device__ __half2 g_hs[NN * 8];     // h (then dis*h after k_scale), fp16, 32MB
__device__ __half2 g_agg[NN * 8];    // layer-1 accumulation in fp16, 32MB
__device__ float   g_h2s[NN];        // dis[i]*h2[i]

// ---------------- fused: degree atomics (LTS) + x@W1 (DRAM/FMA) ----------------
#define NB_PROJ 3907            // ceil(NN/256)
#define NB_DEG  15625           // (NE/4)/256 exactly
#define NB_FUSED (NB_PROJ + NB_DEG)

__global__ void __launch_bounds__(256) k_fused(const float* __restrict__ x,
                                               const float* __restrict__ W1,
                                               const int4* __restrict__ dst4,
                                               const float4* __restrict__ ew4) {
    int bid = blockIdx.x;
    if (bid % 5 == 0) {
        __shared__ float sx[256 * 25];
        __shared__ float sW[25 * 16];
        int pb = bid / 5;
        int i0 = pb * 256;
        int nb = min(256, NN - i0);
        int nf4 = (nb * 25) / 4;
        const float4* xg = (const float4*)(x + (size_t)i0 * 25);
        for (int t = threadIdx.x; t < nf4; t += 256) ((float4*)sx)[t] = __ldcs(xg + t);
        for (int t = threadIdx.x; t < 400; t += 256) sW[t] = W1[t];
        __syncthreads();

        int li = threadIdx.x;
        if (li >= nb) return;
        int i = i0 + li;

        float a[16];
#pragma unroll
        for (int f = 0; f < 16; f++) a[f] = 0.0f;
#pragma unroll
        for (int k = 0; k < 25; k++) {
            float xv = sx[li * 25 + k];
#pragma unroll
            for (int f = 0; f < 16; f++) a[f] = fmaf(xv, sW[k * 16 + f], a[f]);
        }

        __half2 hv[8];
#pragma unroll
        for (int q = 0; q < 8; q++)
            hv[q] = __floats2half2_rn(a[2*q], a[2*q + 1]);
        uint4* hp = (uint4*)(g_hs + (size_t)i * 8);
        hp[0] = *(uint4*)&hv[0];
        hp[1] = *(uint4*)&hv[4];
        PDL_TRIGGER();
    } else {
        int db = bid - bid / 5 - 1;
        int tt = db * 256 + threadIdx.x;          // < NE/4 exactly by grid
        int4 d = __ldcs(dst4 + tt);
        float4 w = __ldcs(ew4 + tt);
        atomicAdd(&g_deg[d.x], w.x);
        atomicAdd(&g_deg[d.y], w.y);
        atomicAdd(&g_deg[d.z], w.z);
        atomicAdd(&g_deg[d.w], w.w);
        PDL_TRIGGER();
    }
}

// scale g_hs by dis[i] in place; write agg self-loop seed (1 node/thread)
__global__ void k_scale() {
    PDL_WAIT();
    int i = blockIdx.x * blockDim.x + threadIdx.x;
    if (i >= NN) return;
    float s = rsqrtf(g_deg[i] + 1.0f);
    uint4* hp = (uint4*)(g_hs + (size_t)i * 8);
    uint4 p0 = hp[0], p1 = hp[1];
    __half2 hv[8];
    const unsigned* pu = &p0.x;
#pragma unroll
    for (int q = 0; q < 4; q++) {
        float2 f = __half22float2(*(const __half2*)&pu[q]);
        hv[q] = __floats2half2_rn(s * f.x, s * f.y);
    }
    const unsigned* pv = &p1.x;
#pragma unroll
    for (int q = 0; q < 4; q++) {
        float2 f = __half22float2(*(const __half2*)&pv[q]);
        hv[4 + q] = __floats2half2_rn(s * f.x, s * f.y);
    }
    uint4 v0 = *(uint4*)&hv[0];
    uint4 v1 = *(uint4*)&hv[4];
    hp[0] = v0; hp[1] = v1;
    uint4* ap = (uint4*)(g_agg + (size_t)i * 8);
    ap[0] = v0; ap[1] = v1;          // self-loop seed (dis*h)
    PDL_TRIGGER();
}

__device__ __forceinline__ void red_v4h(__half2* addr, unsigned a, unsigned b,
                                        unsigned c, unsigned d) {
    asm volatile("red.global.add.noftz.v4.f16x2 [%0], {%1,%2,%3,%4};"
                 :: "l"(addr), "r"(a), "r"(b), "r"(c), "r"(d)
                 : "memory");
}

// layer-1 edge scatter, paired-lane; streams prefetched pre-wait (pure inputs)
__global__ void __launch_bounds__(256) k_agg1(const int* __restrict__ src,
                                              const int* __restrict__ dst,
                                              const float* __restrict__ ew) {
    int half = threadIdx.x & 1;
    int pair = threadIdx.x >> 1;
    int base = blockIdx.x * 1024;                 // grid covers NE exactly
    int   s[8], d[8];
    float w[8];
#pragma unroll
    for (int j = 0; j < 8; j++) {
        int e = base + j * 128 + pair;
        s[j] = __ldg(src + e);
        d[j] = __ldg(dst + e);
        w[j] = __ldg(ew + e);
    }
    PDL_WAIT();
#pragma unroll
    for (int j = 0; j < 8; j++) {
        uint4 p = __ldg((const uint4*)(g_hs + (size_t)s[j] * 8 + half * 4));
        __half2 wh = __float2half2_rn(w[j]);
        const unsigned* pu = &p.x;
        unsigned m[4];
#pragma unroll
        for (int q = 0; q < 4; q++) {
            __half2 r = __hmul2(wh, *(const __half2*)&pu[q]);
            m[q] = *(unsigned*)&r;
        }
        red_v4h(g_agg + (size_t)d[j] * 8 + half * 4, m[0], m[1], m[2], m[3]);
    }
    PDL_TRIGGER();
}

// layer1 finish: u = dis[i]*agg + b1 -> ELU -> h2 = u@W2
__global__ void k_elu_proj2(const float* __restrict__ b1,
                            const float* __restrict__ W2,
                            float* __restrict__ out) {
    __shared__ float sb1[16], sW2[16];
    if (threadIdx.x < 16) { sb1[threadIdx.x] = b1[threadIdx.x]; sW2[threadIdx.x] = W2[threadIdx.x]; }
    __syncthreads();
    PDL_WAIT();

    int i = blockIdx.x * blockDim.x + threadIdx.x;
    if (i >= NN) return;

    const uint4* ap = (const uint4*)(g_agg + (size_t)i * 8);
    uint4 p0 = __ldcs(ap);
    uint4 p1 = __ldcs(ap + 1);
    float s = rsqrtf(g_deg[i] + 1.0f);
    float acc = 0.0f;
    const unsigned* pu = &p0.x;
#pragma unroll
    for (int q = 0; q < 4; q++) {
        float2 f = __half22float2(*(const __half2*)&pu[q]);
        float u0 = fmaf(s, f.x, sb1[2*q]);
        float u1 = fmaf(s, f.y, sb1[2*q+1]);
        u0 = (u0 > 0.0f) ? u0 : (__expf(u0) - 1.0f);
        u1 = (u1 > 0.0f) ? u1 : (__expf(u1) - 1.0f);
        acc = fmaf(u0, sW2[2*q], acc);
        acc = fmaf(u1, sW2[2*q+1], acc);
    }
    const unsigned* pv = &p1.x;
#pragma unroll
    for (int q = 0; q < 4; q++) {
        float2 f = __half22float2(*(const __half2*)&pv[q]);
        float u0 = fmaf(s, f.x, sb1[8+2*q]);
        float u1 = fmaf(s, f.y, sb1[8+2*q+1]);
        u0 = (u0 > 0.0f) ? u0 : (__expf(u0) - 1.0f);
        u1 = (u1 > 0.0f) ? u1 : (__expf(u1) - 1.0f);
        acc = fmaf(u0, sW2[8+2*q], acc);
        acc = fmaf(u1, sW2[8+2*q+1], acc);
    }
    float hs = s * acc;
    g_h2s[i] = hs;
    out[i] = hs;                                   // self-loop seed
    PDL_TRIGGER();
}

__device__ __forceinline__ void red_f32(float* addr, float v) {
    asm volatile("red.global.add.f32 [%0], %1;" :: "l"(addr), "f"(v) : "memory");
}

// layer-2 edge scatter; 8 edges/thread, streams prefetched pre-wait
__global__ void k_agg2(const int4* __restrict__ src4,
                       const int4* __restrict__ dst4,
                       const float4* __restrict__ ew4,
                       float* __restrict__ out) {
    int t = (blockIdx.x * blockDim.x + threadIdx.x) * 2;
    int4 s[2], d[2];
    float4 w[2];
    bool ok[2];
#pragma unroll
    for (int j = 0; j < 2; j++) {
        int tt = t + j;
        ok[j] = (tt < NE / 4);
        if (ok[j]) {
            s[j] = __ldcs(src4 + tt);
            d[j] = __ldcs(dst4 + tt);
            w[j] = __ldcs(ew4 + tt);
        }
    }
    PDL_WAIT();
#pragma unroll
    for (int j = 0; j < 2; j++) {
        if (!ok[j]) break;
        red_f32(&out[d[j].x], w[j].x * __ldg(&g_h2s[s[j].x]));
        red_f32(&out[d[j].y], w[j].y * __ldg(&g_h2s[s[j].y]));
        red_f32(&out[d[j].z], w[j].z * __ldg(&g_h2s[s[j].z]));
        red_f32(&out[d[j].w], w[j].w * __ldg(&g_h2s[s[j].w]));
    }
    PDL_TRIGGER();
}

// final scale: out = dis*out + b2; re-zero g_deg. 4 nodes/thread, vectorized.
__global__ void k_final(float* __restrict__ out, const float* __restrict__ b2) {
    PDL_WAIT();
    int t = blockIdx.x * blockDim.x + threadIdx.x;
    if (t * 4 >= NN) return;
    float bias = b2[0];
    float4* o4 = (float4*)out;
    float4* g4 = (float4*)g_deg;
    float4 o = o4[t];
    float4 g = g4[t];
    o.x = fmaf(rsqrtf(g.x + 1.0f), o.x, bias);
    o.y = fmaf(rsqrtf(g.y + 1.0f), o.y, bias);
    o.z = fmaf(rsqrtf(g.z + 1.0f), o.z, bias);
    o.w = fmaf(rsqrtf(g.w + 1.0f), o.w, bias);
    o4[t] = o;
    g4[t] = make_float4(0.0f, 0.0f, 0.0f, 0.0f);
}

// ---------------- launch ----------------

static void launch_pdl(const void* func, int grid, int block, void** args) {
    cudaLaunchConfig_t cfg = {};
    cfg.gridDim = dim3(grid, 1, 1);
    cfg.blockDim = dim3(block, 1, 1);
    cfg.dynamicSmemBytes = 0;
    cfg.stream = 0;
    cudaLaunchAttribute attr[1];
    attr[0].id = cudaLaunchAttributeProgrammaticStreamSerialization;
    attr[0].val.programmaticStreamSerializationAllowed = 1;
    cfg.attrs = attr;
    cfg.numAttrs = 1;
    cudaLaunchKernelExC(&cfg, func, args);
}

extern "C" void kernel_launch(void* const* d_in, const int* in_sizes, int n_in,
                              void* d_out, int out_size) {
    const float* x    = (const float*)d_in[0];
    const int*   eidx = (const int*)d_in[1];      // [2, E] int32
    const float* ew   = (const float*)d_in[2];
    const float* W1   = (const float*)d_in[3];
    const float* b1   = (const float*)d_in[4];
    const float* W2   = (const float*)d_in[5];
    const float* b2   = (const float*)d_in[6];
    float* out = (float*)d_out;

    const int*    src  = eidx;
    const int*    dst  = eidx + NE;
    const int4*   src4 = (const int4*)eidx;
    const int4*   dst4 = (const int4*)(eidx + NE);
    const float4* ew4  = (const float4*)ew;

    const int TB = 256;
    int nb_nodes = (NN + TB - 1) / TB;
    int nb_final = (NN / 4 + TB - 1) / TB;         // NN % 4 == 0
    int nb_e8    = (NE / 8 + TB - 1) / TB;
    int nb_agg1  = NE / 1024;

    k_fused<<<NB_FUSED, TB>>>(x, W1, dst4, ew4);
    {
        void* a2[] = {};
        launch_pdl((const void*)k_scale, nb_nodes, TB, a2);
    }
    {
        void* a3[] = {(void*)&src, (void*)&dst, (void*)&ew};
        launch_pdl((const void*)k_agg1, nb_agg1, TB, a3);
    }
    {
        void* a4[] = {(void*)&b1, (void*)&W2, (void*)&out};
        launch_pdl((const void*)k_elu_proj2, nb_nodes, TB, a4);
    }
    {
        void* a5[] = {(void*)&src4, (void*)&dst4, (void*)&ew4, (void*)&out};
        launch_pdl((const void*)k_agg2, nb_e8, TB, a5);
    }
    {
        void* a6[] = {(void*)&out, (void*)&b2};
        launch_pdl((const void*)k_final, nb_final, TB, a6);
    }
}

// round 16
// speedup vs baseline: 1.0462x; 1.0066x over previous
#include <cuda_runtime.h>
#include <cuda_fp16.h>
#include <math.h>

#define NN 1000000
#define NE 16000000

// PDL primitives (sm_90+)
#define PDL_TRIGGER() asm volatile("griddepcontrol.launch_dependents;")
#define PDL_WAIT()    asm volatile("griddepcontrol.wait;" ::: "memory")

// ---- scratch (device globals; zero-initialized at load) ----
__device__ float   g_deg[NN];        // re-zeroed by k_final each call
__device__ __half2 g_hs[NN * 8];     // h (then dis*h after k_scale), fp16, 32MB
__device__ __half2 g_agg[NN * 8];    // layer-1 accumulation in fp16, 32MB
__device__ float   g_h2s[NN];        // dis[i]*h2[i]

// ---------------- fused: degree atomics (LTS) + x@W1 (DRAM/FMA) ----------------
#define NB_PROJ 3907            // ceil(NN/256)
#define NB_DEG  15625           // (NE/4)/256 exactly
#define NB_FUSED (NB_PROJ + NB_DEG)

__global__ void __launch_bounds__(256) k_fused(const float* __restrict__ x,
                                               const float* __restrict__ W1,
                                               const int4* __restrict__ dst4,
                                               const float4* __restrict__ ew4) {
    int bid = blockIdx.x;
    if (bid % 5 == 0) {
        // ---- projection: all staging + compute PRE-wait (inputs + smem only) ----
        __shared__ float sx[256 * 25];
        __shared__ float sW[25 * 16];
        int pb = bid / 5;
        int i0 = pb * 256;
        int nb = min(256, NN - i0);
        int nf4 = (nb * 25) / 4;
        const float4* xg = (const float4*)(x + (size_t)i0 * 25);
        for (int t = threadIdx.x; t < nf4; t += 256) ((float4*)sx)[t] = __ldcs(xg + t);
        for (int t = threadIdx.x; t < 400; t += 256) sW[t] = W1[t];
        __syncthreads();

        int li = threadIdx.x;
        if (li >= nb) { PDL_WAIT(); PDL_TRIGGER(); return; }
        int i = i0 + li;

        float a[16];
#pragma unroll
        for (int f = 0; f < 16; f++) a[f] = 0.0f;
#pragma unroll
        for (int k = 0; k < 25; k++) {
            float xv = sx[li * 25 + k];
#pragma unroll
            for (int f = 0; f < 16; f++) a[f] = fmaf(xv, sW[k * 16 + f], a[f]);
        }

        __half2 hv[8];
#pragma unroll
        for (int q = 0; q < 8; q++)
            hv[q] = __floats2half2_rn(a[2*q], a[2*q + 1]);

        PDL_WAIT();                 // order g_hs store after prior replay drains
        uint4* hp = (uint4*)(g_hs + (size_t)i * 8);
        hp[0] = *(uint4*)&hv[0];
        hp[1] = *(uint4*)&hv[4];
        PDL_TRIGGER();
    } else {
        // ---- degree: stream prefetch PRE-wait; atomics after (vs k_final zero) ----
        int db = bid - bid / 5 - 1;
        int tt = db * 256 + threadIdx.x;          // < NE/4 exactly by grid
        int4 d = __ldcs(dst4 + tt);
        float4 w = __ldcs(ew4 + tt);
        PDL_WAIT();
        atomicAdd(&g_deg[d.x], w.x);
        atomicAdd(&g_deg[d.y], w.y);
        atomicAdd(&g_deg[d.z], w.z);
        atomicAdd(&g_deg[d.w], w.w);
        PDL_TRIGGER();
    }
}

// scale g_hs by dis[i] in place; write agg self-loop seed (1 node/thread)
__global__ void k_scale() {
    PDL_WAIT();
    int i = blockIdx.x * blockDim.x + threadIdx.x;
    if (i >= NN) return;
    float s = rsqrtf(g_deg[i] + 1.0f);
    uint4* hp = (uint4*)(g_hs + (size_t)i * 8);
    uint4 p0 = hp[0], p1 = hp[1];
    __half2 hv[8];
    const unsigned* pu = &p0.x;
#pragma unroll
    for (int q = 0; q < 4; q++) {
        float2 f = __half22float2(*(const __half2*)&pu[q]);
        hv[q] = __floats2half2_rn(s * f.x, s * f.y);
    }
    const unsigned* pv = &p1.x;
#pragma unroll
    for (int q = 0; q < 4; q++) {
        float2 f = __half22float2(*(const __half2*)&pv[q]);
        hv[4 + q] = __floats2half2_rn(s * f.x, s * f.y);
    }
    uint4 v0 = *(uint4*)&hv[0];
    uint4 v1 = *(uint4*)&hv[4];
    hp[0] = v0; hp[1] = v1;
    uint4* ap = (uint4*)(g_agg + (size_t)i * 8);
    ap[0] = v0; ap[1] = v1;          // self-loop seed (dis*h)
    PDL_TRIGGER();
}

__device__ __forceinline__ void red_v4h(__half2* addr, unsigned a, unsigned b,
                                        unsigned c, unsigned d) {
    asm volatile("red.global.add.noftz.v4.f16x2 [%0], {%1,%2,%3,%4};"
                 :: "l"(addr), "r"(a), "r"(b), "r"(c), "r"(d)
                 : "memory");
}

// layer-1 edge scatter, paired-lane; streams prefetched pre-wait (pure inputs)
__global__ void __launch_bounds__(256) k_agg1(const int* __restrict__ src,
                                              const int* __restrict__ dst,
                                              const float* __restrict__ ew) {
    int half = threadIdx.x & 1;
    int pair = threadIdx.x >> 1;
    int base = blockIdx.x * 1024;                 // grid covers NE exactly
    int   s[8], d[8];
    float w[8];
#pragma unroll
    for (int j = 0; j < 8; j++) {
        int e = base + j * 128 + pair;
        s[j] = __ldg(src + e);
        d[j] = __ldg(dst + e);
        w[j] = __ldg(ew + e);
    }
    PDL_WAIT();
#pragma unroll
    for (int j = 0; j < 8; j++) {
        uint4 p = __ldg((const uint4*)(g_hs + (size_t)s[j] * 8 + half * 4));
        __half2 wh = __float2half2_rn(w[j]);
        const unsigned* pu = &p.x;
        unsigned m[4];
#pragma unroll
        for (int q = 0; q < 4; q++) {
            __half2 r = __hmul2(wh, *(const __half2*)&pu[q]);
            m[q] = *(unsigned*)&r;
        }
        red_v4h(g_agg + (size_t)d[j] * 8 + half * 4, m[0], m[1], m[2], m[3]);
    }
    PDL_TRIGGER();
}

// layer1 finish: u = dis[i]*agg + b1 -> ELU -> h2 = u@W2
__global__ void k_elu_proj2(const float* __restrict__ b1,
                            const float* __restrict__ W2,
                            float* __restrict__ out) {
    __shared__ float sb1[16], sW2[16];
    if (threadIdx.x < 16) { sb1[threadIdx.x] = b1[threadIdx.x]; sW2[threadIdx.x] = W2[threadIdx.x]; }
    __syncthreads();
    PDL_WAIT();

    int i = blockIdx.x * blockDim.x + threadIdx.x;
    if (i >= NN) return;

    const uint4* ap = (const uint4*)(g_agg + (size_t)i * 8);
    uint4 p0 = __ldcs(ap);
    uint4 p1 = __ldcs(ap + 1);
    float s = rsqrtf(g_deg[i] + 1.0f);
    float acc = 0.0f;
    const unsigned* pu = &p0.x;
#pragma unroll
    for (int q = 0; q < 4; q++) {
        float2 f = __half22float2(*(const __half2*)&pu[q]);
        float u0 = fmaf(s, f.x, sb1[2*q]);
        float u1 = fmaf(s, f.y, sb1[2*q+1]);
        u0 = (u0 > 0.0f) ? u0 : (__expf(u0) - 1.0f);
        u1 = (u1 > 0.0f) ? u1 : (__expf(u1) - 1.0f);
        acc = fmaf(u0, sW2[2*q], acc);
        acc = fmaf(u1, sW2[2*q+1], acc);
    }
    const unsigned* pv = &p1.x;
#pragma unroll
    for (int q = 0; q < 4; q++) {
        float2 f = __half22float2(*(const __half2*)&pv[q]);
        float u0 = fmaf(s, f.x, sb1[8+2*q]);
        float u1 = fmaf(s, f.y, sb1[8+2*q+1]);
        u0 = (u0 > 0.0f) ? u0 : (__expf(u0) - 1.0f);
        u1 = (u1 > 0.0f) ? u1 : (__expf(u1) - 1.0f);
        acc = fmaf(u0, sW2[8+2*q], acc);
        acc = fmaf(u1, sW2[8+2*q+1], acc);
    }
    float hs = s * acc;
    g_h2s[i] = hs;
    out[i] = hs;                                   // self-loop seed
    PDL_TRIGGER();
}

__device__ __forceinline__ void red_f32(float* addr, float v) {
    asm volatile("red.global.add.f32 [%0], %1;" :: "l"(addr), "f"(v) : "memory");
}

// layer-2 edge scatter; 8 edges/thread, streams prefetched pre-wait
__global__ void k_agg2(const int4* __restrict__ src4,
                       const int4* __restrict__ dst4,
                       const float4* __restrict__ ew4,
                       float* __restrict__ out) {
    int t = (blockIdx.x * blockDim.x + threadIdx.x) * 2;
    int4 s[2], d[2];
    float4 w[2];
    bool ok[2];
#pragma unroll
    for (int j = 0; j < 2; j++) {
        int tt = t + j;
        ok[j] = (tt < NE / 4);
        if (ok[j]) {
            s[j] = __ldcs(src4 + tt);
            d[j] = __ldcs(dst4 + tt);
            w[j] = __ldcs(ew4 + tt);
        }
    }
    PDL_WAIT();
#pragma unroll
    for (int j = 0; j < 2; j++) {
        if (!ok[j]) break;
        red_f32(&out[d[j].x], w[j].x * __ldg(&g_h2s[s[j].x]));
        red_f32(&out[d[j].y], w[j].y * __ldg(&g_h2s[s[j].y]));
        red_f32(&out[d[j].z], w[j].z * __ldg(&g_h2s[s[j].z]));
        red_f32(&out[d[j].w], w[j].w * __ldg(&g_h2s[s[j].w]));
    }
    PDL_TRIGGER();
}

// final scale: out = dis*out + b2; re-zero g_deg. 4 nodes/thread, vectorized.
// Triggers the NEXT replay's k_fused (cross-iteration overlap).
__global__ void k_final(float* __restrict__ out, const float* __restrict__ b2) {
    PDL_WAIT();
    int t = blockIdx.x * blockDim.x + threadIdx.x;
    if (t * 4 >= NN) { PDL_TRIGGER(); return; }
    float bias = b2[0];
    float4* o4 = (float4*)out;
    float4* g4 = (float4*)g_deg;
    float4 o = o4[t];
    float4 g = g4[t];
    o.x = fmaf(rsqrtf(g.x + 1.0f), o.x, bias);
    o.y = fmaf(rsqrtf(g.y + 1.0f), o.y, bias);
    o.z = fmaf(rsqrtf(g.z + 1.0f), o.z, bias);
    o.w = fmaf(rsqrtf(g.w + 1.0f), o.w, bias);
    o4[t] = o;
    g4[t] = make_float4(0.0f, 0.0f, 0.0f, 0.0f);
    PDL_TRIGGER();
}

// ---------------- launch ----------------

static void launch_pdl(const void* func, int grid, int block, void** args) {
    cudaLaunchConfig_t cfg = {};
    cfg.gridDim = dim3(grid, 1, 1);
    cfg.blockDim = dim3(block, 1, 1);
    cfg.dynamicSmemBytes = 0;
    cfg.stream = 0;
    cudaLaunchAttribute attr[1];
    attr[0].id = cudaLaunchAttributeProgrammaticStreamSerialization;
    attr[0].val.programmaticStreamSerializationAllowed = 1;
    cfg.attrs = attr;
    cfg.numAttrs = 1;
    cudaLaunchKernelExC(&cfg, func, args);
}

extern "C" void kernel_launch(void* const* d_in, const int* in_sizes, int n_in,
                              void* d_out, int out_size) {
    const float* x    = (const float*)d_in[0];
    const int*   eidx = (const int*)d_in[1];      // [2, E] int32
    const float* ew   = (const float*)d_in[2];
    const float* W1   = (const float*)d_in[3];
    const float* b1   = (const float*)d_in[4];
    const float* W2   = (const float*)d_in[5];
    const float* b2   = (const float*)d_in[6];
    float* out = (float*)d_out;

    const int*    src  = eidx;
    const int*    dst  = eidx + NE;
    const int4*   src4 = (const int4*)eidx;
    const int4*   dst4 = (const int4*)(eidx + NE);
    const float4* ew4  = (const float4*)ew;

    const int TB = 256;
    int nb_nodes = (NN + TB - 1) / TB;
    int nb_final = (NN / 4 + TB - 1) / TB;         // NN % 4 == 0
    int nb_e8    = (NE / 8 + TB - 1) / TB;
    int nb_agg1  = NE / 1024;

    {
        void* a1[] = {(void*)&x, (void*)&W1, (void*)&dst4, (void*)&ew4};
        launch_pdl((const void*)k_fused, NB_FUSED, TB, a1);
    }
    {
        void* a2[] = {};
        launch_pdl((const void*)k_scale, nb_nodes, TB, a2);
    }
    {
        void* a3[] = {(void*)&src, (void*)&dst, (void*)&ew};
        launch_pdl((const void*)k_agg1, nb_agg1, TB, a3);
    }
    {
        void* a4[] = {(void*)&b1, (void*)&W2, (void*)&out};
        launch_pdl((const void*)k_elu_proj2, nb_nodes, TB, a4);
    }
    {
        void* a5[] = {(void*)&src4, (void*)&dst4, (void*)&ew4, (void*)&out};
        launch_pdl((const void*)k_agg2, nb_e8, TB, a5);
    }
    {
        void* a6[] = {(void*)&out, (void*)&b2};
        launch_pdl((const void*)k_final, nb_final, TB, a6);
    }
}